// round 1
// baseline (speedup 1.0000x reference)
#include <cuda_runtime.h>
#include <math.h>

#define Nn 10000
#define Ee 320000
#define Hh 128
#define EPSf 1e-8f

// ---------------- scratch (device globals; no allocations allowed) ----------
__device__ float g_temb[Hh];
__device__ float g_hfeat[2][Nn * Hh];
__device__ float g_x[2][Nn * 3];
__device__ float g_efeat[(size_t)Ee * Hh];   // 164 MB
__device__ float g_aggmsg[Nn * Hh];
__device__ float g_aggtrans[Nn * 3];

__device__ __forceinline__ float siluf(float x) {
    // x * sigmoid(x); __expf(+inf) path gives 0 correctly for very negative x
    return x / (1.0f + __expf(-x));
}

// ---------------- t embedding: silu(t*W1+b1) @ W2 + b2  (tiny) --------------
__global__ void temb_kernel(const float* __restrict__ t,
                            const float* __restrict__ w1, const float* __restrict__ b1,
                            const float* __restrict__ w2, const float* __restrict__ b2) {
    __shared__ float sh[Hh];
    int j = threadIdx.x;
    float tv = t[0];
    sh[j] = siluf(tv * w1[j] + b1[j]);
    __syncthreads();
    float acc = b2[j];
    #pragma unroll 4
    for (int k = 0; k < Hh; k++) acc = fmaf(sh[k], w2[k * Hh + j], acc);
    g_temb[j] = acc;
}

// ---------------- h_feat = h @ Wemb + b + t_emb  (N x 64 x 128) -------------
__global__ void __launch_bounds__(256, 1) hfeat_kernel(
    const float* __restrict__ h, const float* __restrict__ W, const float* __restrict__ B) {
    extern __shared__ float sIn[];  // 64 x 64
    int tid = threadIdx.x;
    int n0 = blockIdx.x * 64;
    for (int idx = tid; idx < 64 * 64; idx += 256) {
        int i = idx >> 6, k = idx & 63;
        int node = n0 + i;
        sIn[idx] = (node < Nn) ? h[node * 64 + k] : 0.f;
    }
    __syncthreads();
    int jc = tid & 31, wp = tid >> 5;
    float acc[8][4];
    #pragma unroll
    for (int r = 0; r < 8; r++) { acc[r][0]=acc[r][1]=acc[r][2]=acc[r][3]=0.f; }
    const float4* Wv = (const float4*)W;
    for (int k = 0; k < 64; k++) {
        float4 w = Wv[k * 32 + jc];
        #pragma unroll
        for (int r = 0; r < 8; r++) {
            float a = sIn[(wp * 8 + r) * 64 + k];
            acc[r][0]=fmaf(a,w.x,acc[r][0]); acc[r][1]=fmaf(a,w.y,acc[r][1]);
            acc[r][2]=fmaf(a,w.z,acc[r][2]); acc[r][3]=fmaf(a,w.w,acc[r][3]);
        }
    }
    float4 bv = ((const float4*)B)[jc];
    float4 tv = ((const float4*)g_temb)[jc];
    #pragma unroll
    for (int r = 0; r < 8; r++) {
        int node = n0 + wp * 8 + r;
        if (node < Nn) {
            float4 o;
            o.x = acc[r][0]+bv.x+tv.x; o.y = acc[r][1]+bv.y+tv.y;
            o.z = acc[r][2]+bv.z+tv.z; o.w = acc[r][3]+bv.w+tv.w;
            ((float4*)(g_hfeat[0] + node * Hh))[jc] = o;
        }
    }
}

// ---------------- edge_feat = edge_attr @ W + b  (E x 16 x 128) -------------
__global__ void __launch_bounds__(256, 1) efeat_kernel(
    const float* __restrict__ ea, const float* __restrict__ W, const float* __restrict__ B) {
    __shared__ float sIn[64 * 16];
    int tid = threadIdx.x;
    int e0 = blockIdx.x * 64;
    for (int idx = tid; idx < 64 * 16; idx += 256) sIn[idx] = ea[e0 * 16 + idx];
    __syncthreads();
    int jc = tid & 31, wp = tid >> 5;
    float acc[8][4];
    #pragma unroll
    for (int r = 0; r < 8; r++) { acc[r][0]=acc[r][1]=acc[r][2]=acc[r][3]=0.f; }
    const float4* Wv = (const float4*)W;
    #pragma unroll
    for (int k = 0; k < 16; k++) {
        float4 w = Wv[k * 32 + jc];
        #pragma unroll
        for (int r = 0; r < 8; r++) {
            float a = sIn[(wp * 8 + r) * 16 + k];
            acc[r][0]=fmaf(a,w.x,acc[r][0]); acc[r][1]=fmaf(a,w.y,acc[r][1]);
            acc[r][2]=fmaf(a,w.z,acc[r][2]); acc[r][3]=fmaf(a,w.w,acc[r][3]);
        }
    }
    float4 bv = ((const float4*)B)[jc];
    #pragma unroll
    for (int r = 0; r < 8; r++) {
        int e = e0 + wp * 8 + r;
        float4 o;
        o.x=acc[r][0]+bv.x; o.y=acc[r][1]+bv.y; o.z=acc[r][2]+bv.z; o.w=acc[r][3]+bv.w;
        ((float4*)(g_efeat + (size_t)e * Hh))[jc] = o;
    }
}

// ---------------- x init copy -----------------------------------------------
__global__ void copyx_kernel(const float* __restrict__ x) {
    int i = blockIdx.x * 256 + threadIdx.x;
    if (i < Nn * 3) g_x[0][i] = x[i];
}

// ---------------- zero accumulators -----------------------------------------
__global__ void zero_kernel() {
    int i = blockIdx.x * 256 + threadIdx.x;
    if (i < Nn * Hh) g_aggmsg[i] = 0.f;
    else if (i < Nn * Hh + Nn * 3) g_aggtrans[i - Nn * Hh] = 0.f;
}

// ---------------- fused edge kernel (64 edges/block, 512 threads) -----------
// edge_in = [h[row](128) | h[col](128) | d2(1) | edge_feat(128)]  -> 385
// h1 = silu(edge_in@W1+b1); m = silu(h1@W2+b2); u = silu(m@C1+cb);
// w = tanh(u . C2); trans = diff/(dist+eps)*w; atomic segment sums by row.
#define SA_STRIDE 388
__global__ void __launch_bounds__(512, 1) edge_kernel(
    const int* __restrict__ rowi, const int* __restrict__ coli,
    const float* __restrict__ W1, const float* __restrict__ B1,
    const float* __restrict__ W2, const float* __restrict__ B2,
    const float* __restrict__ C1, const float* __restrict__ CB,
    const float* __restrict__ C2, int sel) {
    extern __shared__ float sm[];
    float* sA    = sm;                    // 64 x 388
    float* sH    = sA + 64 * SA_STRIDE;   // 64 x 128
    float* sM    = sH + 64 * 128;         // 64 x 128
    float* sDiff = sM + 64 * 128;         // 64 x 3
    float* sDist = sDiff + 64 * 3;        // 64
    int*   sRow  = (int*)(sDist + 64);    // 64
    int*   sCol  = sRow + 64;             // 64

    const float* hc = g_hfeat[sel];
    const float* xc = g_x[sel];
    int tid = threadIdx.x;
    int e0 = blockIdx.x * 64;

    if (tid < 64) {
        int e = e0 + tid;
        int r = rowi[e], c = coli[e];
        sRow[tid] = r; sCol[tid] = c;
        float dx = xc[r*3+0] - xc[c*3+0];
        float dy = xc[r*3+1] - xc[c*3+1];
        float dz = xc[r*3+2] - xc[c*3+2];
        float d2 = dx*dx + dy*dy + dz*dz;
        sDiff[tid*3+0] = dx; sDiff[tid*3+1] = dy; sDiff[tid*3+2] = dz;
        sDist[tid] = sqrtf(d2 + EPSf);
        sA[tid * SA_STRIDE + 256] = d2;
    }
    __syncthreads();
    for (int idx = tid; idx < 64 * Hh; idx += 512) {
        int e = idx >> 7, k = idx & 127;
        sA[e * SA_STRIDE + k]        = hc[sRow[e] * Hh + k];
        sA[e * SA_STRIDE + 128 + k]  = hc[sCol[e] * Hh + k];
        sA[e * SA_STRIDE + 257 + k]  = g_efeat[(size_t)(e0 + e) * Hh + k];
    }
    __syncthreads();

    int jc = tid & 31, wp = tid >> 5;  // 16 warps, 4 edges each
    // ---- GEMM1: K=385 ----
    {
        float acc[4][4];
        #pragma unroll
        for (int r = 0; r < 4; r++) { acc[r][0]=acc[r][1]=acc[r][2]=acc[r][3]=0.f; }
        const float4* Wv = (const float4*)W1;
        for (int k = 0; k < 385; k++) {
            float4 w = Wv[k * 32 + jc];
            #pragma unroll
            for (int r = 0; r < 4; r++) {
                float a = sA[(wp * 4 + r) * SA_STRIDE + k];
                acc[r][0]=fmaf(a,w.x,acc[r][0]); acc[r][1]=fmaf(a,w.y,acc[r][1]);
                acc[r][2]=fmaf(a,w.z,acc[r][2]); acc[r][3]=fmaf(a,w.w,acc[r][3]);
            }
        }
        float4 bv = ((const float4*)B1)[jc];
        #pragma unroll
        for (int r = 0; r < 4; r++) {
            float4 o;
            o.x = siluf(acc[r][0]+bv.x); o.y = siluf(acc[r][1]+bv.y);
            o.z = siluf(acc[r][2]+bv.z); o.w = siluf(acc[r][3]+bv.w);
            ((float4*)sH)[(wp * 4 + r) * 32 + jc] = o;
        }
    }
    __syncthreads();
    // ---- GEMM2: m = silu(sH @ W2 + b2) -> sM ----
    {
        float acc[4][4];
        #pragma unroll
        for (int r = 0; r < 4; r++) { acc[r][0]=acc[r][1]=acc[r][2]=acc[r][3]=0.f; }
        const float4* Wv = (const float4*)W2;
        for (int k = 0; k < 128; k++) {
            float4 w = Wv[k * 32 + jc];
            #pragma unroll
            for (int r = 0; r < 4; r++) {
                float a = sH[(wp * 4 + r) * 128 + k];
                acc[r][0]=fmaf(a,w.x,acc[r][0]); acc[r][1]=fmaf(a,w.y,acc[r][1]);
                acc[r][2]=fmaf(a,w.z,acc[r][2]); acc[r][3]=fmaf(a,w.w,acc[r][3]);
            }
        }
        float4 bv = ((const float4*)B2)[jc];
        #pragma unroll
        for (int r = 0; r < 4; r++) {
            float4 o;
            o.x = siluf(acc[r][0]+bv.x); o.y = siluf(acc[r][1]+bv.y);
            o.z = siluf(acc[r][2]+bv.z); o.w = siluf(acc[r][3]+bv.w);
            ((float4*)sM)[(wp * 4 + r) * 32 + jc] = o;
        }
    }
    __syncthreads();
    // ---- GEMM3: u = silu(sM @ C1 + cb) -> sH ----
    {
        float acc[4][4];
        #pragma unroll
        for (int r = 0; r < 4; r++) { acc[r][0]=acc[r][1]=acc[r][2]=acc[r][3]=0.f; }
        const float4* Wv = (const float4*)C1;
        for (int k = 0; k < 128; k++) {
            float4 w = Wv[k * 32 + jc];
            #pragma unroll
            for (int r = 0; r < 4; r++) {
                float a = sM[(wp * 4 + r) * 128 + k];
                acc[r][0]=fmaf(a,w.x,acc[r][0]); acc[r][1]=fmaf(a,w.y,acc[r][1]);
                acc[r][2]=fmaf(a,w.z,acc[r][2]); acc[r][3]=fmaf(a,w.w,acc[r][3]);
            }
        }
        float4 bv = ((const float4*)CB)[jc];
        #pragma unroll
        for (int r = 0; r < 4; r++) {
            float4 o;
            o.x = siluf(acc[r][0]+bv.x); o.y = siluf(acc[r][1]+bv.y);
            o.z = siluf(acc[r][2]+bv.z); o.w = siluf(acc[r][3]+bv.w);
            ((float4*)sH)[(wp * 4 + r) * 32 + jc] = o;
        }
    }
    __syncthreads();
    // ---- w = tanh(u . C2); coordinate atomics ----
    #pragma unroll
    for (int r = 0; r < 4; r++) {
        int e = wp * 4 + r;
        float p = 0.f;
        #pragma unroll
        for (int k = jc; k < 128; k += 32) p = fmaf(sH[e * 128 + k], C2[k], p);
        p += __shfl_xor_sync(0xffffffffu, p, 16);
        p += __shfl_xor_sync(0xffffffffu, p, 8);
        p += __shfl_xor_sync(0xffffffffu, p, 4);
        p += __shfl_xor_sync(0xffffffffu, p, 2);
        p += __shfl_xor_sync(0xffffffffu, p, 1);
        if (jc == 0) {
            float wsc = tanhf(p);
            float s = wsc / (sDist[e] + EPSf);
            int rw = sRow[e];
            atomicAdd(&g_aggtrans[rw * 3 + 0], sDiff[e * 3 + 0] * s);
            atomicAdd(&g_aggtrans[rw * 3 + 1], sDiff[e * 3 + 1] * s);
            atomicAdd(&g_aggtrans[rw * 3 + 2], sDiff[e * 3 + 2] * s);
        }
    }
    // ---- message atomics: agg_msg[row] += m ----
    for (int idx = tid; idx < 64 * Hh; idx += 512) {
        int e = idx >> 7, k = idx & 127;
        atomicAdd(&g_aggmsg[sRow[e] * Hh + k], sM[e * 128 + k]);
    }
}

// ---------------- node update kernel (64 nodes/block, 256 threads) ----------
__global__ void __launch_bounds__(256, 1) node_kernel(
    const float* __restrict__ mask,
    const float* __restrict__ N1w, const float* __restrict__ NB1,
    const float* __restrict__ N2w, const float* __restrict__ NB2,
    int selr, int selw) {
    extern __shared__ float sm[];
    float* sIn = sm;             // 64 x 256
    float* sH  = sIn + 64 * 256; // 64 x 128
    const float* hc = g_hfeat[selr];
    float* hn = g_hfeat[selw];
    int tid = threadIdx.x;
    int n0 = blockIdx.x * 64;

    for (int idx = tid; idx < 64 * Hh; idx += 256) {
        int i = idx >> 7, k = idx & 127;
        int node = n0 + i;
        float hv = 0.f, av = 0.f;
        if (node < Nn) { hv = hc[node * Hh + k]; av = g_aggmsg[node * Hh + k]; }
        sIn[i * 256 + k] = hv;
        sIn[i * 256 + 128 + k] = av;
    }
    __syncthreads();

    int jc = tid & 31, wp = tid >> 5;
    // GEMM1 K=256
    {
        float acc[8][4];
        #pragma unroll
        for (int r = 0; r < 8; r++) { acc[r][0]=acc[r][1]=acc[r][2]=acc[r][3]=0.f; }
        const float4* Wv = (const float4*)N1w;
        for (int k = 0; k < 256; k++) {
            float4 w = Wv[k * 32 + jc];
            #pragma unroll
            for (int r = 0; r < 8; r++) {
                float a = sIn[(wp * 8 + r) * 256 + k];
                acc[r][0]=fmaf(a,w.x,acc[r][0]); acc[r][1]=fmaf(a,w.y,acc[r][1]);
                acc[r][2]=fmaf(a,w.z,acc[r][2]); acc[r][3]=fmaf(a,w.w,acc[r][3]);
            }
        }
        float4 bv = ((const float4*)NB1)[jc];
        #pragma unroll
        for (int r = 0; r < 8; r++) {
            float4 o;
            o.x = siluf(acc[r][0]+bv.x); o.y = siluf(acc[r][1]+bv.y);
            o.z = siluf(acc[r][2]+bv.z); o.w = siluf(acc[r][3]+bv.w);
            ((float4*)sH)[(wp * 8 + r) * 32 + jc] = o;
        }
    }
    __syncthreads();
    // GEMM2 K=128 ; h_new = h + (. @ N2 + nb2)
    {
        float acc[8][4];
        #pragma unroll
        for (int r = 0; r < 8; r++) { acc[r][0]=acc[r][1]=acc[r][2]=acc[r][3]=0.f; }
        const float4* Wv = (const float4*)N2w;
        for (int k = 0; k < 128; k++) {
            float4 w = Wv[k * 32 + jc];
            #pragma unroll
            for (int r = 0; r < 8; r++) {
                float a = sH[(wp * 8 + r) * 128 + k];
                acc[r][0]=fmaf(a,w.x,acc[r][0]); acc[r][1]=fmaf(a,w.y,acc[r][1]);
                acc[r][2]=fmaf(a,w.z,acc[r][2]); acc[r][3]=fmaf(a,w.w,acc[r][3]);
            }
        }
        float4 bv = ((const float4*)NB2)[jc];
        #pragma unroll
        for (int r = 0; r < 8; r++) {
            int node = n0 + wp * 8 + r;
            if (node < Nn) {
                float4 hv = ((const float4*)(hc + node * Hh))[jc];
                float4 o;
                o.x = hv.x + acc[r][0] + bv.x; o.y = hv.y + acc[r][1] + bv.y;
                o.z = hv.z + acc[r][2] + bv.z; o.w = hv.w + acc[r][3] + bv.w;
                ((float4*)(hn + node * Hh))[jc] = o;
            }
        }
    }
    // x update: x_new = x + agg_trans * mask
    if (tid < 64) {
        int node = n0 + tid;
        if (node < Nn) {
            float mk = mask[node];
            const float* xr = g_x[selr];
            float* xw = g_x[selw];
            xw[node*3+0] = xr[node*3+0] + g_aggtrans[node*3+0] * mk;
            xw[node*3+1] = xr[node*3+1] + g_aggtrans[node*3+1] * mk;
            xw[node*3+2] = xr[node*3+2] + g_aggtrans[node*3+2] * mk;
        }
    }
}

// ---------------- final: v = (x_final - x_in) * mask ------------------------
__global__ void final_kernel(const float* __restrict__ x_in,
                             const float* __restrict__ mask,
                             float* __restrict__ out) {
    int i = blockIdx.x * 256 + threadIdx.x;
    if (i < Nn) {
        float mk = mask[i];
        out[i*3+0] = (g_x[0][i*3+0] - x_in[i*3+0]) * mk;
        out[i*3+1] = (g_x[0][i*3+1] - x_in[i*3+1]) * mk;
        out[i*3+2] = (g_x[0][i*3+2] - x_in[i*3+2]) * mk;
    }
}

// ---------------- launcher ---------------------------------------------------
extern "C" void kernel_launch(void* const* d_in, const int* in_sizes, int n_in,
                              void* d_out, int out_size) {
    const float* h          = (const float*)d_in[0];
    const float* x          = (const float*)d_in[1];
    const int*   edge_index = (const int*)  d_in[2];
    const float* edge_attr  = (const float*)d_in[3];
    const float* t          = (const float*)d_in[4];
    const float* mask       = (const float*)d_in[5];
    const float* time_w1    = (const float*)d_in[6];
    const float* time_b1    = (const float*)d_in[7];
    const float* time_w2    = (const float*)d_in[8];
    const float* time_b2    = (const float*)d_in[9];
    const float* node_emb_w = (const float*)d_in[10];
    const float* node_emb_b = (const float*)d_in[11];
    const float* edge_emb_w = (const float*)d_in[12];
    const float* edge_emb_b = (const float*)d_in[13];
    const float* ew1 = (const float*)d_in[14];
    const float* eb1 = (const float*)d_in[15];
    const float* ew2 = (const float*)d_in[16];
    const float* eb2 = (const float*)d_in[17];
    const float* cw1 = (const float*)d_in[18];
    const float* cb1 = (const float*)d_in[19];
    const float* cw2 = (const float*)d_in[20];
    const float* nw1 = (const float*)d_in[21];
    const float* nb1 = (const float*)d_in[22];
    const float* nw2 = (const float*)d_in[23];
    const float* nb2 = (const float*)d_in[24];
    float* out = (float*)d_out;

    const int* rowi = edge_index;
    const int* coli = edge_index + Ee;

    const int SMEM_EDGE = (64 * SA_STRIDE + 64 * 128 * 2 + 64 * 3 + 64) * 4 + 64 * 2 * 4; // 166400
    const int SMEM_NODE = (64 * 256 + 64 * 128) * 4;                                      // 98304
    const int SMEM_HFEAT = 64 * 64 * 4;

    cudaFuncSetAttribute(edge_kernel, cudaFuncAttributeMaxDynamicSharedMemorySize, SMEM_EDGE);
    cudaFuncSetAttribute(node_kernel, cudaFuncAttributeMaxDynamicSharedMemorySize, SMEM_NODE);

    int nblkN = (Nn + 63) / 64;     // 157
    int nblkE = Ee / 64;            // 5000

    temb_kernel<<<1, 128>>>(t, time_w1, time_b1, time_w2, time_b2);
    hfeat_kernel<<<nblkN, 256, SMEM_HFEAT>>>(h, node_emb_w, node_emb_b);
    copyx_kernel<<<(Nn * 3 + 255) / 256, 256>>>(x);
    efeat_kernel<<<nblkE, 256>>>(edge_attr, edge_emb_w, edge_emb_b);

    for (int l = 0; l < 4; l++) {
        int sr = l & 1;
        int sw = 1 - sr;
        zero_kernel<<<(Nn * Hh + Nn * 3 + 255) / 256, 256>>>();
        edge_kernel<<<nblkE, 512, SMEM_EDGE>>>(
            rowi, coli,
            ew1 + (size_t)l * 385 * Hh, eb1 + l * Hh,
            ew2 + (size_t)l * Hh * Hh,  eb2 + l * Hh,
            cw1 + (size_t)l * Hh * Hh,  cb1 + l * Hh,
            cw2 + (size_t)l * Hh,
            sr);
        node_kernel<<<nblkN, 256, SMEM_NODE>>>(
            mask,
            nw1 + (size_t)l * 256 * Hh, nb1 + l * Hh,
            nw2 + (size_t)l * Hh * Hh,  nb2 + l * Hh,
            sr, sw);
    }

    final_kernel<<<(Nn + 255) / 256, 256>>>(x, mask, out);
}

// round 2
// speedup vs baseline: 2.1656x; 2.1656x over previous
#include <cuda_runtime.h>
#include <math.h>

#define Nn 10000
#define Ee 320000
#define Hh 128
#define EPSf 1e-8f

// ---------------- scratch (device globals; no allocations allowed) ----------
__device__ float g_temb[Hh];
__device__ float g_hfeat[2][Nn * Hh];
__device__ float g_x[2][Nn * 3];
__device__ float g_P[Nn * Hh];        // hf @ W1a  (per layer)
__device__ float g_Q[Nn * Hh];        // hf @ W1b  (per layer)
__device__ float g_CW[16 * Hh];       // edge_emb_w @ W1c (per layer)
__device__ float g_b1eff[Hh];         // b1 + edge_emb_b @ W1c (per layer)
__device__ float g_aggmsg[Nn * Hh];
__device__ float g_aggtrans[Nn * 3];

__device__ __forceinline__ float siluf(float x) {
    return x / (1.0f + __expf(-x));
}

// ---------------- t embedding ------------------------------------------------
__global__ void temb_kernel(const float* __restrict__ t,
                            const float* __restrict__ w1, const float* __restrict__ b1,
                            const float* __restrict__ w2, const float* __restrict__ b2) {
    __shared__ float sh[Hh];
    int j = threadIdx.x;
    float tv = t[0];
    sh[j] = siluf(tv * w1[j] + b1[j]);
    __syncthreads();
    float acc = b2[j];
    #pragma unroll 4
    for (int k = 0; k < Hh; k++) acc = fmaf(sh[k], w2[k * Hh + j], acc);
    g_temb[j] = acc;
}

// ---------------- h_feat = h @ Wemb + b + t_emb ------------------------------
__global__ void __launch_bounds__(256, 1) hfeat_kernel(
    const float* __restrict__ h, const float* __restrict__ W, const float* __restrict__ B) {
    extern __shared__ float sIn[];  // 64 x 64
    int tid = threadIdx.x;
    int n0 = blockIdx.x * 64;
    for (int idx = tid; idx < 64 * 64; idx += 256) {
        int i = idx >> 6, k = idx & 63;
        int node = n0 + i;
        sIn[idx] = (node < Nn) ? h[node * 64 + k] : 0.f;
    }
    __syncthreads();
    int jc = tid & 31, wp = tid >> 5;
    float acc[8][4];
    #pragma unroll
    for (int r = 0; r < 8; r++) { acc[r][0]=acc[r][1]=acc[r][2]=acc[r][3]=0.f; }
    const float4* Wv = (const float4*)W;
    for (int k = 0; k < 64; k++) {
        float4 w = Wv[k * 32 + jc];
        #pragma unroll
        for (int r = 0; r < 8; r++) {
            float a = sIn[(wp * 8 + r) * 64 + k];
            acc[r][0]=fmaf(a,w.x,acc[r][0]); acc[r][1]=fmaf(a,w.y,acc[r][1]);
            acc[r][2]=fmaf(a,w.z,acc[r][2]); acc[r][3]=fmaf(a,w.w,acc[r][3]);
        }
    }
    float4 bv = ((const float4*)B)[jc];
    float4 tv = ((const float4*)g_temb)[jc];
    #pragma unroll
    for (int r = 0; r < 8; r++) {
        int node = n0 + wp * 8 + r;
        if (node < Nn) {
            float4 o;
            o.x = acc[r][0]+bv.x+tv.x; o.y = acc[r][1]+bv.y+tv.y;
            o.z = acc[r][2]+bv.z+tv.z; o.w = acc[r][3]+bv.w+tv.w;
            ((float4*)(g_hfeat[0] + node * Hh))[jc] = o;
        }
    }
}

// ---------------- x init copy ------------------------------------------------
__global__ void copyx_kernel(const float* __restrict__ x) {
    int i = blockIdx.x * 256 + threadIdx.x;
    if (i < Nn * 3) g_x[0][i] = x[i];
}

// ---------------- zero accumulators ------------------------------------------
__global__ void zero_kernel() {
    int i = blockIdx.x * 256 + threadIdx.x;
    if (i < Nn * Hh) g_aggmsg[i] = 0.f;
    else if (i < Nn * Hh + Nn * 3) g_aggtrans[i - Nn * Hh] = 0.f;
}

// ---------------- per-layer setup: CW = eew @ W1c ; b1eff = b1 + eeb @ W1c ---
// W1c = rows [257, 385) of W1 (385 x 128).
__global__ void __launch_bounds__(256, 1) layer_setup_kernel(
    const float* __restrict__ eew, const float* __restrict__ eeb,
    const float* __restrict__ W1, const float* __restrict__ B1) {
    __shared__ float sW[Hh];  // one column of W1c at a time? -> use row-broadcast instead
    (void)sW;
    int tid = threadIdx.x;
    // each thread owns output column j for 8 rows of CW
    for (int o = tid; o < 16 * Hh; o += 256) {
        int i = o >> 7, j = o & 127;
        float acc = 0.f;
        #pragma unroll 4
        for (int k = 0; k < Hh; k++)
            acc = fmaf(eew[i * Hh + k], W1[(257 + k) * Hh + j], acc);
        g_CW[o] = acc;
    }
    if (tid < Hh) {
        float acc = B1[tid];
        #pragma unroll 4
        for (int k = 0; k < Hh; k++)
            acc = fmaf(eeb[k], W1[(257 + k) * Hh + tid], acc);
        g_b1eff[tid] = acc;
    }
}

// ---------------- per-layer: P = hf @ W1a, Q = hf @ W1b ----------------------
// W1a = rows [0,128), W1b = rows [128,256) of W1.
__global__ void __launch_bounds__(256, 1) pq_kernel(
    const float* __restrict__ W1, int sel) {
    extern __shared__ float sIn[];  // 64 x 128
    const float* hc = g_hfeat[sel];
    int tid = threadIdx.x;
    int n0 = blockIdx.x * 64;
    for (int idx = tid; idx < 64 * Hh; idx += 256) {
        int i = idx >> 7, k = idx & 127;
        int node = n0 + i;
        sIn[idx] = (node < Nn) ? hc[node * Hh + k] : 0.f;
    }
    __syncthreads();
    int jc = tid & 31, wp = tid >> 5;
    #pragma unroll
    for (int pass = 0; pass < 2; pass++) {
        const float4* Wv = (const float4*)(W1 + (size_t)pass * 128 * Hh);
        float* dst = pass ? g_Q : g_P;
        float acc[8][4];
        #pragma unroll
        for (int r = 0; r < 8; r++) { acc[r][0]=acc[r][1]=acc[r][2]=acc[r][3]=0.f; }
        for (int k = 0; k < Hh; k++) {
            float4 w = Wv[k * 32 + jc];
            #pragma unroll
            for (int r = 0; r < 8; r++) {
                float a = sIn[(wp * 8 + r) * Hh + k];
                acc[r][0]=fmaf(a,w.x,acc[r][0]); acc[r][1]=fmaf(a,w.y,acc[r][1]);
                acc[r][2]=fmaf(a,w.z,acc[r][2]); acc[r][3]=fmaf(a,w.w,acc[r][3]);
            }
        }
        #pragma unroll
        for (int r = 0; r < 8; r++) {
            int node = n0 + wp * 8 + r;
            if (node < Nn) {
                float4 o; o.x=acc[r][0]; o.y=acc[r][1]; o.z=acc[r][2]; o.w=acc[r][3];
                ((float4*)(dst + node * Hh))[jc] = o;
            }
        }
    }
}

// ---------------- fused edge kernel (64 edges/block, 512 threads) ------------
// h1 = silu(P[row] + Q[col] + d2*w1d + ea@CW + b1eff)
// m  = silu(h1 @ W2 + b2);  u = silu(m @ C1 + cb);  w = tanh(u . C2)
// trans = diff/(dist+eps)*w; atomic segment sums by row.
__global__ void __launch_bounds__(512, 1) edge_kernel(
    const int* __restrict__ rowi, const int* __restrict__ coli,
    const float* __restrict__ ea,
    const float* __restrict__ W1,   // for w1d = row 256
    const float* __restrict__ W2, const float* __restrict__ B2,
    const float* __restrict__ C1, const float* __restrict__ CB,
    const float* __restrict__ C2, int sel) {
    extern __shared__ float sm[];
    float* sH    = sm;                 // 64 x 128
    float* sM    = sH + 64 * Hh;       // 64 x 128
    float* sEA   = sM + 64 * Hh;       // 64 x 16
    float* sCW   = sEA + 64 * 16;      // 16 x 128
    float* sWd   = sCW + 16 * Hh;      // 128
    float* sB1   = sWd + Hh;           // 128
    float* sDiff = sB1 + Hh;           // 64 x 3
    float* sDist = sDiff + 64 * 3;     // 64
    float* sD2   = sDist + 64;         // 64
    int*   sRow  = (int*)(sD2 + 64);   // 64
    int*   sCol  = sRow + 64;          // 64

    const float* xc = g_x[sel];
    int tid = threadIdx.x;
    int e0 = blockIdx.x * 64;

    if (tid < 64) {
        int e = e0 + tid;
        int r = rowi[e], c = coli[e];
        sRow[tid] = r; sCol[tid] = c;
        float dx = xc[r*3+0] - xc[c*3+0];
        float dy = xc[r*3+1] - xc[c*3+1];
        float dz = xc[r*3+2] - xc[c*3+2];
        float d2 = dx*dx + dy*dy + dz*dz;
        sDiff[tid*3+0] = dx; sDiff[tid*3+1] = dy; sDiff[tid*3+2] = dz;
        sD2[tid] = d2;
        sDist[tid] = sqrtf(d2 + EPSf);
    }
    for (int idx = tid; idx < 64 * 16; idx += 512) sEA[idx] = ea[e0 * 16 + idx];
    for (int idx = tid; idx < 16 * Hh; idx += 512) sCW[idx] = g_CW[idx];
    if (tid < Hh) {
        sWd[tid] = W1[256 * Hh + tid];
        sB1[tid] = g_b1eff[tid];
    }
    __syncthreads();

    int jc = tid & 31, wp = tid >> 5;  // 16 warps
    const float4* P4 = (const float4*)g_P;
    const float4* Q4 = (const float4*)g_Q;
    const float4* CW4 = (const float4*)sCW;
    const float4* Wd4 = (const float4*)sWd;
    const float4* B14 = (const float4*)sB1;

    // ---- fused GEMM1 replacement: each warp does 4 edges, 32 lanes over j --
    #pragma unroll
    for (int r = 0; r < 4; r++) {
        int e = wp * 4 + r;
        int rw = sRow[e], cl = sCol[e];
        float d2 = sD2[e];
        float4 v  = P4[rw * 32 + jc];
        float4 q  = Q4[cl * 32 + jc];
        float4 wd = Wd4[jc];
        float4 bv = B14[jc];
        v.x += q.x + d2*wd.x + bv.x;
        v.y += q.y + d2*wd.y + bv.y;
        v.z += q.z + d2*wd.z + bv.z;
        v.w += q.w + d2*wd.w + bv.w;
        #pragma unroll
        for (int k = 0; k < 16; k++) {
            float a = sEA[e * 16 + k];
            float4 w = CW4[k * 32 + jc];
            v.x = fmaf(a, w.x, v.x); v.y = fmaf(a, w.y, v.y);
            v.z = fmaf(a, w.z, v.z); v.w = fmaf(a, w.w, v.w);
        }
        float4 o;
        o.x = siluf(v.x); o.y = siluf(v.y); o.z = siluf(v.z); o.w = siluf(v.w);
        ((float4*)sH)[e * 32 + jc] = o;
    }
    __syncthreads();

    // ---- GEMM2: m = silu(sH @ W2 + b2) -> sM ----
    {
        float acc[4][4];
        #pragma unroll
        for (int r = 0; r < 4; r++) { acc[r][0]=acc[r][1]=acc[r][2]=acc[r][3]=0.f; }
        const float4* Wv = (const float4*)W2;
        for (int k = 0; k < Hh; k++) {
            float4 w = Wv[k * 32 + jc];
            #pragma unroll
            for (int r = 0; r < 4; r++) {
                float a = sH[(wp * 4 + r) * Hh + k];
                acc[r][0]=fmaf(a,w.x,acc[r][0]); acc[r][1]=fmaf(a,w.y,acc[r][1]);
                acc[r][2]=fmaf(a,w.z,acc[r][2]); acc[r][3]=fmaf(a,w.w,acc[r][3]);
            }
        }
        float4 bv = ((const float4*)B2)[jc];
        #pragma unroll
        for (int r = 0; r < 4; r++) {
            float4 o;
            o.x = siluf(acc[r][0]+bv.x); o.y = siluf(acc[r][1]+bv.y);
            o.z = siluf(acc[r][2]+bv.z); o.w = siluf(acc[r][3]+bv.w);
            ((float4*)sM)[(wp * 4 + r) * 32 + jc] = o;
        }
    }
    __syncthreads();
    // ---- GEMM3: u = silu(sM @ C1 + cb) -> sH ----
    {
        float acc[4][4];
        #pragma unroll
        for (int r = 0; r < 4; r++) { acc[r][0]=acc[r][1]=acc[r][2]=acc[r][3]=0.f; }
        const float4* Wv = (const float4*)C1;
        for (int k = 0; k < Hh; k++) {
            float4 w = Wv[k * 32 + jc];
            #pragma unroll
            for (int r = 0; r < 4; r++) {
                float a = sM[(wp * 4 + r) * Hh + k];
                acc[r][0]=fmaf(a,w.x,acc[r][0]); acc[r][1]=fmaf(a,w.y,acc[r][1]);
                acc[r][2]=fmaf(a,w.z,acc[r][2]); acc[r][3]=fmaf(a,w.w,acc[r][3]);
            }
        }
        float4 bv = ((const float4*)CB)[jc];
        #pragma unroll
        for (int r = 0; r < 4; r++) {
            float4 o;
            o.x = siluf(acc[r][0]+bv.x); o.y = siluf(acc[r][1]+bv.y);
            o.z = siluf(acc[r][2]+bv.z); o.w = siluf(acc[r][3]+bv.w);
            ((float4*)sH)[(wp * 4 + r) * 32 + jc] = o;
        }
    }
    __syncthreads();
    // ---- w = tanh(u . C2); coordinate atomics ----
    #pragma unroll
    for (int r = 0; r < 4; r++) {
        int e = wp * 4 + r;
        float p = 0.f;
        #pragma unroll
        for (int k = jc; k < Hh; k += 32) p = fmaf(sH[e * Hh + k], C2[k], p);
        p += __shfl_xor_sync(0xffffffffu, p, 16);
        p += __shfl_xor_sync(0xffffffffu, p, 8);
        p += __shfl_xor_sync(0xffffffffu, p, 4);
        p += __shfl_xor_sync(0xffffffffu, p, 2);
        p += __shfl_xor_sync(0xffffffffu, p, 1);
        if (jc == 0) {
            float wsc = tanhf(p);
            float s = wsc / (sDist[e] + EPSf);
            int rw = sRow[e];
            atomicAdd(&g_aggtrans[rw * 3 + 0], sDiff[e * 3 + 0] * s);
            atomicAdd(&g_aggtrans[rw * 3 + 1], sDiff[e * 3 + 1] * s);
            atomicAdd(&g_aggtrans[rw * 3 + 2], sDiff[e * 3 + 2] * s);
        }
    }
    // ---- message atomics: agg_msg[row] += m ----
    for (int idx = tid; idx < 64 * Hh; idx += 512) {
        int e = idx >> 7, k = idx & 127;
        atomicAdd(&g_aggmsg[sRow[e] * Hh + k], sM[e * Hh + k]);
    }
}

// ---------------- node update kernel (64 nodes/block, 256 threads) -----------
__global__ void __launch_bounds__(256, 1) node_kernel(
    const float* __restrict__ mask,
    const float* __restrict__ N1w, const float* __restrict__ NB1,
    const float* __restrict__ N2w, const float* __restrict__ NB2,
    int selr, int selw) {
    extern __shared__ float sm[];
    float* sIn = sm;             // 64 x 256
    float* sH  = sIn + 64 * 256; // 64 x 128
    const float* hc = g_hfeat[selr];
    float* hn = g_hfeat[selw];
    int tid = threadIdx.x;
    int n0 = blockIdx.x * 64;

    for (int idx = tid; idx < 64 * Hh; idx += 256) {
        int i = idx >> 7, k = idx & 127;
        int node = n0 + i;
        float hv = 0.f, av = 0.f;
        if (node < Nn) { hv = hc[node * Hh + k]; av = g_aggmsg[node * Hh + k]; }
        sIn[i * 256 + k] = hv;
        sIn[i * 256 + 128 + k] = av;
    }
    __syncthreads();

    int jc = tid & 31, wp = tid >> 5;
    {
        float acc[8][4];
        #pragma unroll
        for (int r = 0; r < 8; r++) { acc[r][0]=acc[r][1]=acc[r][2]=acc[r][3]=0.f; }
        const float4* Wv = (const float4*)N1w;
        for (int k = 0; k < 256; k++) {
            float4 w = Wv[k * 32 + jc];
            #pragma unroll
            for (int r = 0; r < 8; r++) {
                float a = sIn[(wp * 8 + r) * 256 + k];
                acc[r][0]=fmaf(a,w.x,acc[r][0]); acc[r][1]=fmaf(a,w.y,acc[r][1]);
                acc[r][2]=fmaf(a,w.z,acc[r][2]); acc[r][3]=fmaf(a,w.w,acc[r][3]);
            }
        }
        float4 bv = ((const float4*)NB1)[jc];
        #pragma unroll
        for (int r = 0; r < 8; r++) {
            float4 o;
            o.x = siluf(acc[r][0]+bv.x); o.y = siluf(acc[r][1]+bv.y);
            o.z = siluf(acc[r][2]+bv.z); o.w = siluf(acc[r][3]+bv.w);
            ((float4*)sH)[(wp * 8 + r) * 32 + jc] = o;
        }
    }
    __syncthreads();
    {
        float acc[8][4];
        #pragma unroll
        for (int r = 0; r < 8; r++) { acc[r][0]=acc[r][1]=acc[r][2]=acc[r][3]=0.f; }
        const float4* Wv = (const float4*)N2w;
        for (int k = 0; k < Hh; k++) {
            float4 w = Wv[k * 32 + jc];
            #pragma unroll
            for (int r = 0; r < 8; r++) {
                float a = sH[(wp * 8 + r) * Hh + k];
                acc[r][0]=fmaf(a,w.x,acc[r][0]); acc[r][1]=fmaf(a,w.y,acc[r][1]);
                acc[r][2]=fmaf(a,w.z,acc[r][2]); acc[r][3]=fmaf(a,w.w,acc[r][3]);
            }
        }
        float4 bv = ((const float4*)NB2)[jc];
        #pragma unroll
        for (int r = 0; r < 8; r++) {
            int node = n0 + wp * 8 + r;
            if (node < Nn) {
                float4 hv = ((const float4*)(hc + node * Hh))[jc];
                float4 o;
                o.x = hv.x + acc[r][0] + bv.x; o.y = hv.y + acc[r][1] + bv.y;
                o.z = hv.z + acc[r][2] + bv.z; o.w = hv.w + acc[r][3] + bv.w;
                ((float4*)(hn + node * Hh))[jc] = o;
            }
        }
    }
    if (tid < 64) {
        int node = n0 + tid;
        if (node < Nn) {
            float mk = mask[node];
            const float* xr = g_x[selr];
            float* xw = g_x[selw];
            xw[node*3+0] = xr[node*3+0] + g_aggtrans[node*3+0] * mk;
            xw[node*3+1] = xr[node*3+1] + g_aggtrans[node*3+1] * mk;
            xw[node*3+2] = xr[node*3+2] + g_aggtrans[node*3+2] * mk;
        }
    }
}

// ---------------- final: v = (x_final - x_in) * mask -------------------------
__global__ void final_kernel(const float* __restrict__ x_in,
                             const float* __restrict__ mask,
                             float* __restrict__ out) {
    int i = blockIdx.x * 256 + threadIdx.x;
    if (i < Nn) {
        float mk = mask[i];
        out[i*3+0] = (g_x[0][i*3+0] - x_in[i*3+0]) * mk;
        out[i*3+1] = (g_x[0][i*3+1] - x_in[i*3+1]) * mk;
        out[i*3+2] = (g_x[0][i*3+2] - x_in[i*3+2]) * mk;
    }
}

// ---------------- launcher ----------------------------------------------------
extern "C" void kernel_launch(void* const* d_in, const int* in_sizes, int n_in,
                              void* d_out, int out_size) {
    const float* h          = (const float*)d_in[0];
    const float* x          = (const float*)d_in[1];
    const int*   edge_index = (const int*)  d_in[2];
    const float* edge_attr  = (const float*)d_in[3];
    const float* t          = (const float*)d_in[4];
    const float* mask       = (const float*)d_in[5];
    const float* time_w1    = (const float*)d_in[6];
    const float* time_b1    = (const float*)d_in[7];
    const float* time_w2    = (const float*)d_in[8];
    const float* time_b2    = (const float*)d_in[9];
    const float* node_emb_w = (const float*)d_in[10];
    const float* node_emb_b = (const float*)d_in[11];
    const float* edge_emb_w = (const float*)d_in[12];
    const float* edge_emb_b = (const float*)d_in[13];
    const float* ew1 = (const float*)d_in[14];
    const float* eb1 = (const float*)d_in[15];
    const float* ew2 = (const float*)d_in[16];
    const float* eb2 = (const float*)d_in[17];
    const float* cw1 = (const float*)d_in[18];
    const float* cb1 = (const float*)d_in[19];
    const float* cw2 = (const float*)d_in[20];
    const float* nw1 = (const float*)d_in[21];
    const float* nb1 = (const float*)d_in[22];
    const float* nw2 = (const float*)d_in[23];
    const float* nb2 = (const float*)d_in[24];
    float* out = (float*)d_out;

    const int* rowi = edge_index;
    const int* coli = edge_index + Ee;

    // edge smem: sH+sM (2*8192) + sEA 1024 + sCW 2048 + sWd/sB1 256 + diff/dist/d2 320 + idx 128
    const int SMEM_EDGE = (64*Hh*2 + 64*16 + 16*Hh + 2*Hh + 64*3 + 64 + 64) * 4 + 64 * 2 * 4;
    const int SMEM_NODE = (64 * 256 + 64 * Hh) * 4;
    const int SMEM_64x128 = 64 * Hh * 4;
    const int SMEM_HFEAT = 64 * 64 * 4;

    cudaFuncSetAttribute(edge_kernel, cudaFuncAttributeMaxDynamicSharedMemorySize, SMEM_EDGE);
    cudaFuncSetAttribute(node_kernel, cudaFuncAttributeMaxDynamicSharedMemorySize, SMEM_NODE);
    cudaFuncSetAttribute(pq_kernel,  cudaFuncAttributeMaxDynamicSharedMemorySize, SMEM_64x128);

    int nblkN = (Nn + 63) / 64;     // 157
    int nblkE = Ee / 64;            // 5000

    temb_kernel<<<1, 128>>>(t, time_w1, time_b1, time_w2, time_b2);
    hfeat_kernel<<<nblkN, 256, SMEM_HFEAT>>>(h, node_emb_w, node_emb_b);
    copyx_kernel<<<(Nn * 3 + 255) / 256, 256>>>(x);

    for (int l = 0; l < 4; l++) {
        int sr = l & 1;
        int sw = 1 - sr;
        const float* W1 = ew1 + (size_t)l * 385 * Hh;
        zero_kernel<<<(Nn * Hh + Nn * 3 + 255) / 256, 256>>>();
        layer_setup_kernel<<<1, 256>>>(edge_emb_w, edge_emb_b, W1, eb1 + l * Hh);
        pq_kernel<<<nblkN, 256, SMEM_64x128>>>(W1, sr);
        edge_kernel<<<nblkE, 512, SMEM_EDGE>>>(
            rowi, coli, edge_attr, W1,
            ew2 + (size_t)l * Hh * Hh,  eb2 + l * Hh,
            cw1 + (size_t)l * Hh * Hh,  cb1 + l * Hh,
            cw2 + (size_t)l * Hh,
            sr);
        node_kernel<<<nblkN, 256, SMEM_NODE>>>(
            mask,
            nw1 + (size_t)l * 256 * Hh, nb1 + l * Hh,
            nw2 + (size_t)l * Hh * Hh,  nb2 + l * Hh,
            sr, sw);
    }

    final_kernel<<<(Nn + 255) / 256, 256>>>(x, mask, out);
}

// round 5
// speedup vs baseline: 4.7249x; 2.1818x over previous
#include <cuda_runtime.h>
#include <cuda_bf16.h>
#include <math.h>
#include <stdint.h>

#define Nn 10000
#define Ee 320000
#define Hh 128
#define EPSf 1e-8f
#define NTILES 2500        // 128 edges per tile
#define EDGE_GRID 148
#define EDGE_THREADS 512

// ---------------- scratch ----------------------------------------------------
__device__ float g_temb[Hh];
__device__ float g_hfeat[2][Nn * Hh];
__device__ float g_x[2][Nn * 3];
__device__ float g_P[Nn * Hh];
__device__ float g_Q[Nn * Hh];
__device__ float g_CW[16 * Hh];
__device__ float g_b1eff[Hh];
__device__ float g_aggmsg[Nn * Hh];
__device__ float g_aggtrans[Nn * 3];

__device__ __forceinline__ float siluf(float x) { return x / (1.0f + __expf(-x)); }

__device__ __forceinline__ void mma16(float* d, const uint32_t* a, uint32_t b0, uint32_t b1) {
    asm volatile("mma.sync.aligned.m16n8k16.row.col.f32.bf16.bf16.f32 "
        "{%0,%1,%2,%3}, {%4,%5,%6,%7}, {%8,%9}, {%0,%1,%2,%3};"
        : "+f"(d[0]), "+f"(d[1]), "+f"(d[2]), "+f"(d[3])
        : "r"(a[0]), "r"(a[1]), "r"(a[2]), "r"(a[3]), "r"(b0), "r"(b1));
}

// pack two fp32 into bf16x2 (hi) and residual bf16x2 (lo)
__device__ __forceinline__ void split2(float x0, float x1, uint32_t& hi, uint32_t& lo) {
    __nv_bfloat162 h = __floats2bfloat162_rn(x0, x1);   // .x = x0 (low half)
    float h0 = __bfloat162float(__low2bfloat16(h));
    float h1 = __bfloat162float(__high2bfloat16(h));
    __nv_bfloat162 l = __floats2bfloat162_rn(x0 - h0, x1 - h1);
    hi = *(uint32_t*)&h;
    lo = *(uint32_t*)&l;
}

// ---------------- t embedding ------------------------------------------------
__global__ void temb_kernel(const float* __restrict__ t,
                            const float* __restrict__ w1, const float* __restrict__ b1,
                            const float* __restrict__ w2, const float* __restrict__ b2) {
    __shared__ float sh[Hh];
    int j = threadIdx.x;
    float tv = t[0];
    sh[j] = siluf(tv * w1[j] + b1[j]);
    __syncthreads();
    float acc = b2[j];
    #pragma unroll 4
    for (int k = 0; k < Hh; k++) acc = fmaf(sh[k], w2[k * Hh + j], acc);
    g_temb[j] = acc;
}

// ---------------- h_feat = h @ Wemb + b + t_emb ------------------------------
__global__ void __launch_bounds__(256, 1) hfeat_kernel(
    const float* __restrict__ h, const float* __restrict__ W, const float* __restrict__ B) {
    extern __shared__ float sIn[];
    int tid = threadIdx.x;
    int n0 = blockIdx.x * 64;
    for (int idx = tid; idx < 64 * 64; idx += 256) {
        int i = idx >> 6, k = idx & 63;
        int node = n0 + i;
        sIn[idx] = (node < Nn) ? h[node * 64 + k] : 0.f;
    }
    __syncthreads();
    int jc = tid & 31, wp = tid >> 5;
    float acc[8][4];
    #pragma unroll
    for (int r = 0; r < 8; r++) { acc[r][0]=acc[r][1]=acc[r][2]=acc[r][3]=0.f; }
    const float4* Wv = (const float4*)W;
    for (int k = 0; k < 64; k++) {
        float4 w = Wv[k * 32 + jc];
        #pragma unroll
        for (int r = 0; r < 8; r++) {
            float a = sIn[(wp * 8 + r) * 64 + k];
            acc[r][0]=fmaf(a,w.x,acc[r][0]); acc[r][1]=fmaf(a,w.y,acc[r][1]);
            acc[r][2]=fmaf(a,w.z,acc[r][2]); acc[r][3]=fmaf(a,w.w,acc[r][3]);
        }
    }
    float4 bv = ((const float4*)B)[jc];
    float4 tv = ((const float4*)g_temb)[jc];
    #pragma unroll
    for (int r = 0; r < 8; r++) {
        int node = n0 + wp * 8 + r;
        if (node < Nn) {
            float4 o;
            o.x = acc[r][0]+bv.x+tv.x; o.y = acc[r][1]+bv.y+tv.y;
            o.z = acc[r][2]+bv.z+tv.z; o.w = acc[r][3]+bv.w+tv.w;
            ((float4*)(g_hfeat[0] + node * Hh))[jc] = o;
        }
    }
}

// ---------------- x init copy ------------------------------------------------
__global__ void copyx_kernel(const float* __restrict__ x) {
    int i = blockIdx.x * 256 + threadIdx.x;
    if (i < Nn * 3) g_x[0][i] = x[i];
}

// ---------------- zero accumulators ------------------------------------------
__global__ void zero_kernel() {
    int i = blockIdx.x * 256 + threadIdx.x;
    if (i < Nn * Hh) g_aggmsg[i] = 0.f;
    else if (i < Nn * Hh + Nn * 3) g_aggtrans[i - Nn * Hh] = 0.f;
}

// ---------------- per-layer setup: CW = eew @ W1c ; b1eff = b1 + eeb @ W1c ---
__global__ void __launch_bounds__(256, 1) layer_setup_kernel(
    const float* __restrict__ eew, const float* __restrict__ eeb,
    const float* __restrict__ W1, const float* __restrict__ B1) {
    int tid = threadIdx.x;
    for (int o = tid; o < 16 * Hh; o += 256) {
        int i = o >> 7, j = o & 127;
        float acc = 0.f;
        #pragma unroll 4
        for (int k = 0; k < Hh; k++)
            acc = fmaf(eew[i * Hh + k], W1[(257 + k) * Hh + j], acc);
        g_CW[o] = acc;
    }
    if (tid < Hh) {
        float acc = B1[tid];
        #pragma unroll 4
        for (int k = 0; k < Hh; k++)
            acc = fmaf(eeb[k], W1[(257 + k) * Hh + tid], acc);
        g_b1eff[tid] = acc;
    }
}

// ---------------- per-layer: P = hf @ W1a, Q = hf @ W1b ----------------------
__global__ void __launch_bounds__(256, 1) pq_kernel(
    const float* __restrict__ W1, int sel) {
    extern __shared__ float sIn[];
    const float* hc = g_hfeat[sel];
    int tid = threadIdx.x;
    int n0 = blockIdx.x * 64;
    for (int idx = tid; idx < 64 * Hh; idx += 256) {
        int i = idx >> 7, k = idx & 127;
        int node = n0 + i;
        sIn[idx] = (node < Nn) ? hc[node * Hh + k] : 0.f;
    }
    __syncthreads();
    int jc = tid & 31, wp = tid >> 5;
    #pragma unroll
    for (int pass = 0; pass < 2; pass++) {
        const float4* Wv = (const float4*)(W1 + (size_t)pass * 128 * Hh);
        float* dst = pass ? g_Q : g_P;
        float acc[8][4];
        #pragma unroll
        for (int r = 0; r < 8; r++) { acc[r][0]=acc[r][1]=acc[r][2]=acc[r][3]=0.f; }
        for (int k = 0; k < Hh; k++) {
            float4 w = Wv[k * 32 + jc];
            #pragma unroll
            for (int r = 0; r < 8; r++) {
                float a = sIn[(wp * 8 + r) * Hh + k];
                acc[r][0]=fmaf(a,w.x,acc[r][0]); acc[r][1]=fmaf(a,w.y,acc[r][1]);
                acc[r][2]=fmaf(a,w.z,acc[r][2]); acc[r][3]=fmaf(a,w.w,acc[r][3]);
            }
        }
        #pragma unroll
        for (int r = 0; r < 8; r++) {
            int node = n0 + wp * 8 + r;
            if (node < Nn) {
                float4 o; o.x=acc[r][0]; o.y=acc[r][1]; o.z=acc[r][2]; o.w=acc[r][3];
                ((float4*)(dst + node * Hh))[jc] = o;
            }
        }
    }
}

// ---------------- persistent bf16-split mma edge kernel ----------------------
// 128 edges/tile; warp w -> mi = w&3 (rows), ni = w>>2 (cols).
// A/B stored as packed bf16x2 pairs along k: hi and lo components.
// smem uint offsets:
#define O_W2H  0            // 128n x 68
#define O_W2L  8704
#define O_C1H  17408
#define O_C1L  26112
#define O_AH   34816        // 128row x 68
#define O_AL   43520
#define O_EA   52224        // 128 x 16 floats
#define O_CW   54272        // 16 x 128 floats
#define O_WD   56320
#define O_B1   56448
#define O_B2   56576
#define O_CB   56704
#define O_C2   56832
#define O_DIFF 56960        // 128*3
#define O_DIST 57344
#define O_D2   57472
#define O_PART 57600
#define O_ROW  57728
#define O_COL  57856
#define SMEM_EDGE_WORDS 57984

__global__ void __launch_bounds__(EDGE_THREADS, 1) edge_mma_kernel(
    const int* __restrict__ rowi, const int* __restrict__ coli,
    const float* __restrict__ ea,
    const float* __restrict__ W1,     // row 256 = w1_d
    const float* __restrict__ W2g, const float* __restrict__ B2,
    const float* __restrict__ C1g, const float* __restrict__ CB,
    const float* __restrict__ C2, int sel) {
    extern __shared__ float F[];
    uint32_t* U = (uint32_t*)F;
    uint32_t* sW2H = U + O_W2H;
    uint32_t* sW2L = U + O_W2L;
    uint32_t* sC1H = U + O_C1H;
    uint32_t* sC1L = U + O_C1L;
    uint32_t* sAH  = U + O_AH;
    uint32_t* sAL  = U + O_AL;
    float* sEA = F + O_EA;
    float* sCW = F + O_CW;
    float* sWd = F + O_WD;
    float* sB1 = F + O_B1;
    float* sB2 = F + O_B2;
    float* sCB = F + O_CB;
    float* sC2 = F + O_C2;
    float* sDiff = F + O_DIFF;
    float* sDist = F + O_DIST;
    float* sD2v  = F + O_D2;
    float* sPart = F + O_PART;
    int* sRow = (int*)(F + O_ROW);
    int* sCol = (int*)(F + O_COL);

    int tid = threadIdx.x;
    int lane = tid & 31, w = tid >> 5;
    int mi = w & 3, ni = w >> 2;
    int g = lane >> 2, tg = lane & 3;

    const float* xc = g_x[sel];

    // ---- preamble: stage weights split into bf16 hi/lo, packed (k,k+1) ----
    // idx -> kp = idx>>7 (k-pair), n = idx&127 (coalesced over n)
    for (int idx = tid; idx < 64 * 128; idx += EDGE_THREADS) {
        int kp = idx >> 7, n = idx & 127;
        uint32_t hi, lo;
        split2(W2g[(2 * kp) * 128 + n], W2g[(2 * kp + 1) * 128 + n], hi, lo);
        sW2H[n * 68 + kp] = hi;
        sW2L[n * 68 + kp] = lo;
        split2(C1g[(2 * kp) * 128 + n], C1g[(2 * kp + 1) * 128 + n], hi, lo);
        sC1H[n * 68 + kp] = hi;
        sC1L[n * 68 + kp] = lo;
    }
    for (int idx = tid; idx < 16 * 128; idx += EDGE_THREADS) sCW[idx] = g_CW[idx];
    if (tid < Hh) {
        sWd[tid] = W1[256 * Hh + tid];
        sB1[tid] = g_b1eff[tid];
        sB2[tid] = B2[tid];
        sCB[tid] = CB[tid];
        sC2[tid] = C2[tid];
    }
    __syncthreads();

    for (int tile = blockIdx.x; tile < NTILES; tile += gridDim.x) {
        int e0 = tile * 128;

        // ---- S0: geometry + ea staging ----
        if (tid < 128) {
            int eg = e0 + tid;
            int r = rowi[eg], c = coli[eg];
            sRow[tid] = r; sCol[tid] = c;
            float dx = xc[r*3+0] - xc[c*3+0];
            float dy = xc[r*3+1] - xc[c*3+1];
            float dz = xc[r*3+2] - xc[c*3+2];
            float d2 = dx*dx + dy*dy + dz*dz;
            sDiff[tid*3+0] = dx; sDiff[tid*3+1] = dy; sDiff[tid*3+2] = dz;
            sD2v[tid] = d2;
            sDist[tid] = sqrtf(d2 + EPSf);
            sPart[tid] = 0.f;
        }
        {
            int e = tid >> 2, q = tid & 3;
            float4 v = ((const float4*)(ea + (size_t)(e0 + e) * 16))[q];
            float* d = sEA + e * 16 + q * 4;
            d[0] = v.x; d[1] = v.y; d[2] = v.z; d[3] = v.w;
        }
        __syncthreads();

        // ---- S1: scalar GEMM1: h1 = silu(P[row]+Q[col]+d2*wd+b1 + ea@CW) ----
        {
            int jc = lane;
            float acc[8][4];
            float4 wd = ((const float4*)sWd)[jc];
            float4 b1 = ((const float4*)sB1)[jc];
            #pragma unroll
            for (int r = 0; r < 8; r++) {
                int e = w * 8 + r;
                int rw = sRow[e], cl = sCol[e];
                float d2 = sD2v[e];
                float4 p = ((const float4*)(g_P + (size_t)rw * Hh))[jc];
                float4 q = ((const float4*)(g_Q + (size_t)cl * Hh))[jc];
                acc[r][0] = p.x + q.x + fmaf(d2, wd.x, b1.x);
                acc[r][1] = p.y + q.y + fmaf(d2, wd.y, b1.y);
                acc[r][2] = p.z + q.z + fmaf(d2, wd.z, b1.z);
                acc[r][3] = p.w + q.w + fmaf(d2, wd.w, b1.w);
            }
            const float4* CW4 = (const float4*)sCW;
            #pragma unroll
            for (int k = 0; k < 16; k++) {
                float4 cw = CW4[k * 32 + jc];
                #pragma unroll
                for (int r = 0; r < 8; r++) {
                    float a = sEA[(w * 8 + r) * 16 + k];
                    acc[r][0] = fmaf(a, cw.x, acc[r][0]);
                    acc[r][1] = fmaf(a, cw.y, acc[r][1]);
                    acc[r][2] = fmaf(a, cw.z, acc[r][2]);
                    acc[r][3] = fmaf(a, cw.w, acc[r][3]);
                }
            }
            #pragma unroll
            for (int r = 0; r < 8; r++) {
                int e = w * 8 + r;
                float s0 = siluf(acc[r][0]), s1 = siluf(acc[r][1]);
                float s2 = siluf(acc[r][2]), s3 = siluf(acc[r][3]);
                uint32_t h0, l0, h1p, l1;
                split2(s0, s1, h0, l0);
                split2(s2, s3, h1p, l1);
                // k-pairs 2jc, 2jc+1 -> vectorized 64-bit stores (conflict-free)
                *(uint2*)(sAH + e * 68 + 2 * jc) = make_uint2(h0, h1p);
                *(uint2*)(sAL + e * 68 + 2 * jc) = make_uint2(l0, l1);
            }
        }
        __syncthreads();

        float d[2][4][4];

        // ---- S2: GEMM2 mma (bf16 split x3): m_pre = h1 @ W2 ----
        #pragma unroll
        for (int mt = 0; mt < 2; mt++)
            #pragma unroll
            for (int j = 0; j < 4; j++)
                d[mt][j][0] = d[mt][j][1] = d[mt][j][2] = d[mt][j][3] = 0.f;
        #pragma unroll
        for (int ks = 0; ks < 8; ks++) {
            uint32_t ah[2][4], al[2][4];
            #pragma unroll
            for (int mt = 0; mt < 2; mt++) {
                int base = (mi * 32 + mt * 16 + g) * 68 + ks * 8 + tg;
                ah[mt][0] = sAH[base];          ah[mt][1] = sAH[base + 8 * 68];
                ah[mt][2] = sAH[base + 4];      ah[mt][3] = sAH[base + 8 * 68 + 4];
                al[mt][0] = sAL[base];          al[mt][1] = sAL[base + 8 * 68];
                al[mt][2] = sAL[base + 4];      al[mt][3] = sAL[base + 8 * 68 + 4];
            }
            #pragma unroll
            for (int j = 0; j < 4; j++) {
                int bi = (ni * 32 + j * 8 + g) * 68 + ks * 8 + tg;
                uint32_t bh0 = sW2H[bi], bh1 = sW2H[bi + 4];
                uint32_t bl0 = sW2L[bi], bl1 = sW2L[bi + 4];
                mma16(d[0][j], ah[0], bh0, bh1);
                mma16(d[1][j], ah[1], bh0, bh1);
                mma16(d[0][j], ah[0], bl0, bl1);
                mma16(d[1][j], ah[1], bl0, bl1);
                mma16(d[0][j], al[0], bh0, bh1);
                mma16(d[1][j], al[1], bh0, bh1);
            }
        }
        __syncthreads();   // all warps done reading sA

        // ---- S2e: m = silu(+b2): red to aggmsg + store split m to sA ----
        #pragma unroll
        for (int mt = 0; mt < 2; mt++) {
            int er0 = mi * 32 + mt * 16 + g;
            int er1 = er0 + 8;
            int rw0 = sRow[er0], rw1 = sRow[er1];
            #pragma unroll
            for (int j = 0; j < 4; j++) {
                int c = ni * 32 + j * 8 + 2 * tg;
                float m00 = siluf(d[mt][j][0] + sB2[c]);
                float m01 = siluf(d[mt][j][1] + sB2[c + 1]);
                float m10 = siluf(d[mt][j][2] + sB2[c]);
                float m11 = siluf(d[mt][j][3] + sB2[c + 1]);
                asm volatile("red.global.add.v2.f32 [%0], {%1,%2};"
                             :: "l"(g_aggmsg + (size_t)rw0 * Hh + c), "f"(m00), "f"(m01) : "memory");
                asm volatile("red.global.add.v2.f32 [%0], {%1,%2};"
                             :: "l"(g_aggmsg + (size_t)rw1 * Hh + c), "f"(m10), "f"(m11) : "memory");
                uint32_t hi, lo;
                split2(m00, m01, hi, lo);
                sAH[er0 * 68 + (c >> 1)] = hi;
                sAL[er0 * 68 + (c >> 1)] = lo;
                split2(m10, m11, hi, lo);
                sAH[er1 * 68 + (c >> 1)] = hi;
                sAL[er1 * 68 + (c >> 1)] = lo;
            }
        }
        __syncthreads();

        // ---- S3: GEMM3 mma (bf16 split x3): u_pre = m @ C1 ----
        #pragma unroll
        for (int mt = 0; mt < 2; mt++)
            #pragma unroll
            for (int j = 0; j < 4; j++)
                d[mt][j][0] = d[mt][j][1] = d[mt][j][2] = d[mt][j][3] = 0.f;
        #pragma unroll
        for (int ks = 0; ks < 8; ks++) {
            uint32_t ah[2][4], al[2][4];
            #pragma unroll
            for (int mt = 0; mt < 2; mt++) {
                int base = (mi * 32 + mt * 16 + g) * 68 + ks * 8 + tg;
                ah[mt][0] = sAH[base];          ah[mt][1] = sAH[base + 8 * 68];
                ah[mt][2] = sAH[base + 4];      ah[mt][3] = sAH[base + 8 * 68 + 4];
                al[mt][0] = sAL[base];          al[mt][1] = sAL[base + 8 * 68];
                al[mt][2] = sAL[base + 4];      al[mt][3] = sAL[base + 8 * 68 + 4];
            }
            #pragma unroll
            for (int j = 0; j < 4; j++) {
                int bi = (ni * 32 + j * 8 + g) * 68 + ks * 8 + tg;
                uint32_t bh0 = sC1H[bi], bh1 = sC1H[bi + 4];
                uint32_t bl0 = sC1L[bi], bl1 = sC1L[bi + 4];
                mma16(d[0][j], ah[0], bh0, bh1);
                mma16(d[1][j], ah[1], bh0, bh1);
                mma16(d[0][j], ah[0], bl0, bl1);
                mma16(d[1][j], ah[1], bl0, bl1);
                mma16(d[0][j], al[0], bh0, bh1);
                mma16(d[1][j], al[1], bh0, bh1);
            }
        }

        // ---- S3e: u = silu(+cb); per-row partial dot with C2 ----
        {
            float prt[2][2];
            prt[0][0] = prt[0][1] = prt[1][0] = prt[1][1] = 0.f;
            #pragma unroll
            for (int mt = 0; mt < 2; mt++) {
                #pragma unroll
                for (int j = 0; j < 4; j++) {
                    int c = ni * 32 + j * 8 + 2 * tg;
                    float c2a = sC2[c], c2b = sC2[c + 1];
                    float u00 = siluf(d[mt][j][0] + sCB[c]);
                    float u01 = siluf(d[mt][j][1] + sCB[c + 1]);
                    float u10 = siluf(d[mt][j][2] + sCB[c]);
                    float u11 = siluf(d[mt][j][3] + sCB[c + 1]);
                    prt[mt][0] += u00 * c2a + u01 * c2b;
                    prt[mt][1] += u10 * c2a + u11 * c2b;
                }
            }
            #pragma unroll
            for (int mt = 0; mt < 2; mt++) {
                #pragma unroll
                for (int rh = 0; rh < 2; rh++) {
                    float p = prt[mt][rh];
                    p += __shfl_xor_sync(0xffffffffu, p, 1);
                    p += __shfl_xor_sync(0xffffffffu, p, 2);
                    if (tg == 0)
                        atomicAdd(&sPart[mi * 32 + mt * 16 + rh * 8 + g], p);
                }
            }
        }
        __syncthreads();

        // ---- S4: coordinate atomics ----
        if (tid < 128) {
            float wsc = tanhf(sPart[tid]);
            float s = wsc / (sDist[tid] + EPSf);
            int rw = sRow[tid];
            atomicAdd(&g_aggtrans[rw * 3 + 0], sDiff[tid * 3 + 0] * s);
            atomicAdd(&g_aggtrans[rw * 3 + 1], sDiff[tid * 3 + 1] * s);
            atomicAdd(&g_aggtrans[rw * 3 + 2], sDiff[tid * 3 + 2] * s);
        }
        __syncthreads();
    }
}

// ---------------- node update kernel -----------------------------------------
__global__ void __launch_bounds__(256, 1) node_kernel(
    const float* __restrict__ mask,
    const float* __restrict__ N1w, const float* __restrict__ NB1,
    const float* __restrict__ N2w, const float* __restrict__ NB2,
    int selr, int selw) {
    extern __shared__ float sm[];
    float* sIn = sm;
    float* sH  = sIn + 64 * 256;
    const float* hc = g_hfeat[selr];
    float* hn = g_hfeat[selw];
    int tid = threadIdx.x;
    int n0 = blockIdx.x * 64;

    for (int idx = tid; idx < 64 * Hh; idx += 256) {
        int i = idx >> 7, k = idx & 127;
        int node = n0 + i;
        float hv = 0.f, av = 0.f;
        if (node < Nn) { hv = hc[node * Hh + k]; av = g_aggmsg[node * Hh + k]; }
        sIn[i * 256 + k] = hv;
        sIn[i * 256 + 128 + k] = av;
    }
    __syncthreads();

    int jc = tid & 31, wp = tid >> 5;
    {
        float acc[8][4];
        #pragma unroll
        for (int r = 0; r < 8; r++) { acc[r][0]=acc[r][1]=acc[r][2]=acc[r][3]=0.f; }
        const float4* Wv = (const float4*)N1w;
        for (int k = 0; k < 256; k++) {
            float4 w = Wv[k * 32 + jc];
            #pragma unroll
            for (int r = 0; r < 8; r++) {
                float a = sIn[(wp * 8 + r) * 256 + k];
                acc[r][0]=fmaf(a,w.x,acc[r][0]); acc[r][1]=fmaf(a,w.y,acc[r][1]);
                acc[r][2]=fmaf(a,w.z,acc[r][2]); acc[r][3]=fmaf(a,w.w,acc[r][3]);
            }
        }
        float4 bv = ((const float4*)NB1)[jc];
        #pragma unroll
        for (int r = 0; r < 8; r++) {
            float4 o;
            o.x = siluf(acc[r][0]+bv.x); o.y = siluf(acc[r][1]+bv.y);
            o.z = siluf(acc[r][2]+bv.z); o.w = siluf(acc[r][3]+bv.w);
            ((float4*)sH)[(wp * 8 + r) * 32 + jc] = o;
        }
    }
    __syncthreads();
    {
        float acc[8][4];
        #pragma unroll
        for (int r = 0; r < 8; r++) { acc[r][0]=acc[r][1]=acc[r][2]=acc[r][3]=0.f; }
        const float4* Wv = (const float4*)N2w;
        for (int k = 0; k < Hh; k++) {
            float4 w = Wv[k * 32 + jc];
            #pragma unroll
            for (int r = 0; r < 8; r++) {
                float a = sH[(wp * 8 + r) * Hh + k];
                acc[r][0]=fmaf(a,w.x,acc[r][0]); acc[r][1]=fmaf(a,w.y,acc[r][1]);
                acc[r][2]=fmaf(a,w.z,acc[r][2]); acc[r][3]=fmaf(a,w.w,acc[r][3]);
            }
        }
        float4 bv = ((const float4*)NB2)[jc];
        #pragma unroll
        for (int r = 0; r < 8; r++) {
            int node = n0 + wp * 8 + r;
            if (node < Nn) {
                float4 hv = ((const float4*)(hc + node * Hh))[jc];
                float4 o;
                o.x = hv.x + acc[r][0] + bv.x; o.y = hv.y + acc[r][1] + bv.y;
                o.z = hv.z + acc[r][2] + bv.z; o.w = hv.w + acc[r][3] + bv.w;
                ((float4*)(hn + node * Hh))[jc] = o;
            }
        }
    }
    if (tid < 64) {
        int node = n0 + tid;
        if (node < Nn) {
            float mk = mask[node];
            const float* xr = g_x[selr];
            float* xw = g_x[selw];
            xw[node*3+0] = xr[node*3+0] + g_aggtrans[node*3+0] * mk;
            xw[node*3+1] = xr[node*3+1] + g_aggtrans[node*3+1] * mk;
            xw[node*3+2] = xr[node*3+2] + g_aggtrans[node*3+2] * mk;
        }
    }
}

// ---------------- final ------------------------------------------------------
__global__ void final_kernel(const float* __restrict__ x_in,
                             const float* __restrict__ mask,
                             float* __restrict__ out) {
    int i = blockIdx.x * 256 + threadIdx.x;
    if (i < Nn) {
        float mk = mask[i];
        out[i*3+0] = (g_x[0][i*3+0] - x_in[i*3+0]) * mk;
        out[i*3+1] = (g_x[0][i*3+1] - x_in[i*3+1]) * mk;
        out[i*3+2] = (g_x[0][i*3+2] - x_in[i*3+2]) * mk;
    }
}

// ---------------- launcher ----------------------------------------------------
extern "C" void kernel_launch(void* const* d_in, const int* in_sizes, int n_in,
                              void* d_out, int out_size) {
    const float* h          = (const float*)d_in[0];
    const float* x          = (const float*)d_in[1];
    const int*   edge_index = (const int*)  d_in[2];
    const float* edge_attr  = (const float*)d_in[3];
    const float* t          = (const float*)d_in[4];
    const float* mask       = (const float*)d_in[5];
    const float* time_w1    = (const float*)d_in[6];
    const float* time_b1    = (const float*)d_in[7];
    const float* time_w2    = (const float*)d_in[8];
    const float* time_b2    = (const float*)d_in[9];
    const float* node_emb_w = (const float*)d_in[10];
    const float* node_emb_b = (const float*)d_in[11];
    const float* edge_emb_w = (const float*)d_in[12];
    const float* edge_emb_b = (const float*)d_in[13];
    const float* ew1 = (const float*)d_in[14];
    const float* eb1 = (const float*)d_in[15];
    const float* ew2 = (const float*)d_in[16];
    const float* eb2 = (const float*)d_in[17];
    const float* cw1 = (const float*)d_in[18];
    const float* cb1 = (const float*)d_in[19];
    const float* cw2 = (const float*)d_in[20];
    const float* nw1 = (const float*)d_in[21];
    const float* nb1 = (const float*)d_in[22];
    const float* nw2 = (const float*)d_in[23];
    const float* nb2 = (const float*)d_in[24];
    float* out = (float*)d_out;

    const int* rowi = edge_index;
    const int* coli = edge_index + Ee;

    const int SMEM_EDGE = SMEM_EDGE_WORDS * 4;   // 231936
    const int SMEM_NODE = (64 * 256 + 64 * Hh) * 4;
    const int SMEM_64x128 = 64 * Hh * 4;
    const int SMEM_HFEAT = 64 * 64 * 4;

    cudaFuncSetAttribute(edge_mma_kernel, cudaFuncAttributeMaxDynamicSharedMemorySize, SMEM_EDGE);
    cudaFuncSetAttribute(node_kernel, cudaFuncAttributeMaxDynamicSharedMemorySize, SMEM_NODE);
    cudaFuncSetAttribute(pq_kernel,  cudaFuncAttributeMaxDynamicSharedMemorySize, SMEM_64x128);

    int nblkN = (Nn + 63) / 64;

    temb_kernel<<<1, 128>>>(t, time_w1, time_b1, time_w2, time_b2);
    hfeat_kernel<<<nblkN, 256, SMEM_HFEAT>>>(h, node_emb_w, node_emb_b);
    copyx_kernel<<<(Nn * 3 + 255) / 256, 256>>>(x);

    for (int l = 0; l < 4; l++) {
        int sr = l & 1;
        int sw = 1 - sr;
        const float* W1 = ew1 + (size_t)l * 385 * Hh;
        zero_kernel<<<(Nn * Hh + Nn * 3 + 255) / 256, 256>>>();
        layer_setup_kernel<<<1, 256>>>(edge_emb_w, edge_emb_b, W1, eb1 + l * Hh);
        pq_kernel<<<nblkN, 256, SMEM_64x128>>>(W1, sr);
        edge_mma_kernel<<<EDGE_GRID, EDGE_THREADS, SMEM_EDGE>>>(
            rowi, coli, edge_attr, W1,
            ew2 + (size_t)l * Hh * Hh,  eb2 + l * Hh,
            cw1 + (size_t)l * Hh * Hh,  cb1 + l * Hh,
            cw2 + (size_t)l * Hh,
            sr);
        node_kernel<<<nblkN, 256, SMEM_NODE>>>(
            mask,
            nw1 + (size_t)l * 256 * Hh, nb1 + l * Hh,
            nw2 + (size_t)l * Hh * Hh,  nb2 + l * Hh,
            sr, sw);
    }

    final_kernel<<<(Nn + 255) / 256, 256>>>(x, mask, out);
}